// round 14
// baseline (speedup 1.0000x reference)
#include <cuda_runtime.h>

// ---------------------------------------------------------------------------
// ComplexSwinAttention — FFMA2 pipeline, round 14:
//  - qkv/proj GEMMs: double-buffered smem, ONE barrier per k0-step
//  - attn: FFMA2 for QK (m-pairs) and AV (d-pairs via transposed V)
//  K1 qkv_gemm : Wqkv(768x256 cplx) @ X(256x65536 cplx) -> g_qkv planar
//  K2 attn     : per (window, head) complex attention    -> g_att planar
//  K3 proj_gemm: Wproj(256x256 cplx) @ g_att, REAL part -> d_out
// ---------------------------------------------------------------------------

typedef unsigned long long ull;

__device__ float g_qkv_r[50331648];   // [768][65536]
__device__ float g_qkv_i[50331648];
__device__ float g_att_r[16777216];   // [256][65536]
__device__ float g_att_i[16777216];

__device__ __forceinline__ float gldf(const float* p, long off, long lim)
{
    return (off >= 0 && off < lim) ? __ldg(p + off) : 0.f;
}
__device__ __forceinline__ int gldi(const int* p, long off, long lim)
{
    return (off >= 0 && off < lim) ? __ldg(p + off) : 0;
}
__device__ __forceinline__ float4 guarded_ld4(const float* p, long off, long lim)
{
    if (off >= 0 && off + 3 < lim) return *(const float4*)(p + off);
    return make_float4(0.f, 0.f, 0.f, 0.f);
}
__device__ __forceinline__ ull pk2(float lo, float hi)
{
    ull r; asm("mov.b64 %0,{%1,%2};" : "=l"(r) : "f"(lo), "f"(hi)); return r;
}
__device__ __forceinline__ void upk2(ull v, float& lo, float& hi)
{
    asm("mov.b64 {%0,%1},%2;" : "=f"(lo), "=f"(hi) : "l"(v));
}
__device__ __forceinline__ ull ffma2(ull a, ull b, ull c)
{
    ull d; asm("fma.rn.f32x2 %0,%1,%2,%3;" : "=l"(d) : "l"(a), "l"(b), "l"(c));
    return d;
}

// ---------------------------------------------------------------------------
// K1: qkv complex GEMM. Tile 64x128, K=256 in 16-steps, double-buffered.
// Dyn smem: 2 stages x 42240 B = 84480 B. 2 CTAs/SM.
// Stage layout (ulls): w_rr[1056] w_ii[1056] w_ni[1056] | xs_r/xs_i floats.
// ---------------------------------------------------------------------------
#define QKV_STAGE_ULL 5280

__global__ __launch_bounds__(256, 2) void qkv_gemm(
    const float* __restrict__ wr, const float* __restrict__ wi,
    const float* __restrict__ xr, const float* __restrict__ xi,
    long wlim, long xlim)
{
    extern __shared__ __align__(16) ull smq[];

    const int t = threadIdx.x;
    const long colBase = (long)blockIdx.x * 128;
    const int rowBase = blockIdx.y * 64;

    const int wrow = t >> 2, wk4 = (t & 3) << 2;
    const long wbase = (long)(rowBase + wrow) * 256 + wk4;

    const int k0a = t >> 5;            // 0..7 ; second slot k0a+8
    const int j0a = (t & 31) << 2;     // 0..124
    const long ja = colBase + j0a;
    const long jblk = (ja >> 6) * 16384 + (ja & 63);

    const int tx8 = (t & 15) << 3, ty4 = (t >> 4) << 2;

    ull c_re[4][4], c_im[4][4];
    #pragma unroll
    for (int i = 0; i < 4; ++i)
        #pragma unroll
        for (int j = 0; j < 4; ++j) { c_re[i][j] = 0ull; c_im[i][j] = 0ull; }

    float4 wa, wb, xa0, xb0, xa1, xb1;

    // prologue: load k0=0, store stage 0
    wa  = guarded_ld4(wr, wbase, wlim);
    wb  = guarded_ld4(wi, wbase, wlim);
    xa0 = guarded_ld4(xr, jblk + (long)k0a * 64, xlim);
    xb0 = guarded_ld4(xi, jblk + (long)k0a * 64, xlim);
    xa1 = guarded_ld4(xr, jblk + (long)(k0a + 8) * 64, xlim);
    xb1 = guarded_ld4(xi, jblk + (long)(k0a + 8) * 64, xlim);
    {
        ull* bw = smq;
        float* xsr = (float*)(bw + 3168);
        float* xsi = xsr + 2112;
        float wva[4] = {wa.x, wa.y, wa.z, wa.w};
        float wvb[4] = {wb.x, wb.y, wb.z, wb.w};
        #pragma unroll
        for (int q = 0; q < 4; ++q) {
            bw[(wk4 + q) * 66 + wrow]        = pk2(wva[q], wva[q]);
            bw[1056 + (wk4 + q) * 66 + wrow] = pk2(wvb[q], wvb[q]);
            bw[2112 + (wk4 + q) * 66 + wrow] = pk2(-wvb[q], -wvb[q]);
        }
        *(float4*)&xsr[k0a * 132 + j0a] = xa0;
        *(float4*)&xsi[k0a * 132 + j0a] = xb0;
        *(float4*)&xsr[(k0a + 8) * 132 + j0a] = xa1;
        *(float4*)&xsi[(k0a + 8) * 132 + j0a] = xb1;
    }
    __syncthreads();

    for (int s = 0; s < 16; ++s) {
        if (s < 15) {
            long k0n = (long)(s + 1) * 16;
            wa  = guarded_ld4(wr, wbase + k0n, wlim);
            wb  = guarded_ld4(wi, wbase + k0n, wlim);
            xa0 = guarded_ld4(xr, jblk + (k0n + k0a) * 64, xlim);
            xb0 = guarded_ld4(xi, jblk + (k0n + k0a) * 64, xlim);
            xa1 = guarded_ld4(xr, jblk + (k0n + k0a + 8) * 64, xlim);
            xb1 = guarded_ld4(xi, jblk + (k0n + k0a + 8) * 64, xlim);
        }
        {
            ull* bw = smq + (s & 1) * QKV_STAGE_ULL;
            const ull* w_rr = bw;
            const ull* w_ii = bw + 1056;
            const ull* w_ni = bw + 2112;
            const float* xsr = (const float*)(bw + 3168);
            const float* xsi = xsr + 2112;
            #pragma unroll
            for (int kk = 0; kk < 16; ++kk) {
                ulonglong2 arr0 = *(const ulonglong2*)&w_rr[kk * 66 + ty4];
                ulonglong2 arr1 = *(const ulonglong2*)&w_rr[kk * 66 + ty4 + 2];
                ulonglong2 aii0 = *(const ulonglong2*)&w_ii[kk * 66 + ty4];
                ulonglong2 aii1 = *(const ulonglong2*)&w_ii[kk * 66 + ty4 + 2];
                ulonglong2 ani0 = *(const ulonglong2*)&w_ni[kk * 66 + ty4];
                ulonglong2 ani1 = *(const ulonglong2*)&w_ni[kk * 66 + ty4 + 2];
                ulonglong2 br0 = *(const ulonglong2*)&xsr[kk * 132 + tx8];
                ulonglong2 br1 = *(const ulonglong2*)&xsr[kk * 132 + tx8 + 4];
                ulonglong2 bi0 = *(const ulonglong2*)&xsi[kk * 132 + tx8];
                ulonglong2 bi1 = *(const ulonglong2*)&xsi[kk * 132 + tx8 + 4];
                ull arr[4] = {arr0.x, arr0.y, arr1.x, arr1.y};
                ull aii[4] = {aii0.x, aii0.y, aii1.x, aii1.y};
                ull ani[4] = {ani0.x, ani0.y, ani1.x, ani1.y};
                ull bre[4] = {br0.x, br0.y, br1.x, br1.y};
                ull bim[4] = {bi0.x, bi0.y, bi1.x, bi1.y};
                #pragma unroll
                for (int i = 0; i < 4; ++i)
                    #pragma unroll
                    for (int j = 0; j < 4; ++j) {
                        c_re[i][j] = ffma2(arr[i], bre[j], c_re[i][j]);
                        c_re[i][j] = ffma2(ani[i], bim[j], c_re[i][j]);
                        c_im[i][j] = ffma2(arr[i], bim[j], c_im[i][j]);
                        c_im[i][j] = ffma2(aii[i], bre[j], c_im[i][j]);
                    }
            }
        }
        if (s < 15) {
            ull* bw = smq + ((s + 1) & 1) * QKV_STAGE_ULL;
            float* xsr = (float*)(bw + 3168);
            float* xsi = xsr + 2112;
            float wva[4] = {wa.x, wa.y, wa.z, wa.w};
            float wvb[4] = {wb.x, wb.y, wb.z, wb.w};
            #pragma unroll
            for (int q = 0; q < 4; ++q) {
                bw[(wk4 + q) * 66 + wrow]        = pk2(wva[q], wva[q]);
                bw[1056 + (wk4 + q) * 66 + wrow] = pk2(wvb[q], wvb[q]);
                bw[2112 + (wk4 + q) * 66 + wrow] = pk2(-wvb[q], -wvb[q]);
            }
            *(float4*)&xsr[k0a * 132 + j0a] = xa0;
            *(float4*)&xsi[k0a * 132 + j0a] = xb0;
            *(float4*)&xsr[(k0a + 8) * 132 + j0a] = xa1;
            *(float4*)&xsi[(k0a + 8) * 132 + j0a] = xb1;
        }
        __syncthreads();
    }

    #pragma unroll
    for (int i = 0; i < 4; ++i) {
        long row = rowBase + ty4 + i;
        #pragma unroll
        for (int j = 0; j < 4; ++j) {
            long col = colBase + tx8 + 2 * j;
            *(ull*)&g_qkv_r[row * 65536 + col] = c_re[i][j];
            *(ull*)&g_qkv_i[row * 65536 + col] = c_im[i][j];
        }
    }
}

// ---------------------------------------------------------------------------
// K2: attention per (window, head). 256 threads, dyn smem 84992 B, FFMA2.
// Layout (floats): qr[2048] qi[2048] kr[2048] ki[2048]
//                  vr_t[2304] vi_t[2304] (stride 36, [m][d])
//                  sr[4224] si[4224]    (stride 66, [n][m])
// ---------------------------------------------------------------------------
__global__ __launch_bounds__(256) void attn_kernel(
    const float* __restrict__ bt, const int* __restrict__ ri,
    long btlim, long rilim)
{
    extern __shared__ __align__(16) float sm[];
    float* qr = sm;
    float* qi = qr + 2048;
    float* kr = qi + 2048;
    float* ki = kr + 2048;
    float* vrt = ki + 2048;        // [64][36]
    float* vit = vrt + 2304;
    float* sr = vit + 2304;        // [64][66]
    float* si = sr + 4224;

    const int b = blockIdx.x, h = blockIdx.y;
    const int t = threadIdx.x;
    const long jb = (long)b * 64;
    const float scale = 0.17677669529663687f;   // 32^-0.5

    #pragma unroll
    for (int rep = 0; rep < 2; ++rep) {
        int slot = rep * 256 + t;
        int d = slot >> 4, n4 = (slot & 15) << 2;
        long go = (long)(h * 32 + d) * 65536 + jb + n4;
        int so = d * 64 + n4;
        *(float4*)&qr[so] = *(const float4*)&g_qkv_r[go];
        *(float4*)&qi[so] = *(const float4*)&g_qkv_i[go];
        *(float4*)&kr[so] = *(const float4*)&g_qkv_r[go + 256l * 65536];
        *(float4*)&ki[so] = *(const float4*)&g_qkv_i[go + 256l * 65536];
        float4 vR = *(const float4*)&g_qkv_r[go + 512l * 65536];
        float4 vI = *(const float4*)&g_qkv_i[go + 512l * 65536];
        vrt[(n4 + 0) * 36 + d] = vR.x; vrt[(n4 + 1) * 36 + d] = vR.y;
        vrt[(n4 + 2) * 36 + d] = vR.z; vrt[(n4 + 3) * 36 + d] = vR.w;
        vit[(n4 + 0) * 36 + d] = vI.x; vit[(n4 + 1) * 36 + d] = vI.y;
        vit[(n4 + 2) * 36 + d] = vI.z; vit[(n4 + 3) * 36 + d] = vI.w;
    }
    __syncthreads();

    // ---- S = scale * q conj(k)^T + bias ; micro 4n x 2 m-pairs (FFMA2) ----
    {
        const int n0 = (t >> 4) << 2, m0 = (t & 15) << 2;
        ull re[4][2], im[4][2];
        #pragma unroll
        for (int i = 0; i < 4; ++i) { re[i][0]=re[i][1]=0ull; im[i][0]=im[i][1]=0ull; }
        #pragma unroll 4
        for (int d = 0; d < 32; ++d) {
            float4 q4r = *(const float4*)&qr[d * 64 + n0];
            float4 q4i = *(const float4*)&qi[d * 64 + n0];
            float qR[4] = {q4r.x, q4r.y, q4r.z, q4r.w};
            float qI[4] = {q4i.x, q4i.y, q4i.z, q4i.w};
            ulonglong2 krp = *(const ulonglong2*)&kr[d * 64 + m0];
            ulonglong2 kip = *(const ulonglong2*)&ki[d * 64 + m0];
            ull kR[2] = {krp.x, krp.y};
            ull kI[2] = {kip.x, kip.y};
            #pragma unroll
            for (int i = 0; i < 4; ++i) {
                ull arr = pk2(qR[i], qR[i]);
                ull aii = pk2(qI[i], qI[i]);
                ull nrr = pk2(-qR[i], -qR[i]);
                #pragma unroll
                for (int p = 0; p < 2; ++p) {
                    // re += qR*kR + qI*kI ; im += qI*kR - qR*kI
                    re[i][p] = ffma2(arr, kR[p], re[i][p]);
                    re[i][p] = ffma2(aii, kI[p], re[i][p]);
                    im[i][p] = ffma2(aii, kR[p], im[i][p]);
                    im[i][p] = ffma2(nrr, kI[p], im[i][p]);
                }
            }
        }
        #pragma unroll
        for (int i = 0; i < 4; ++i) {
            int n = n0 + i;
            #pragma unroll
            for (int p = 0; p < 2; ++p) {
                float r0, r1, u0, u1;
                upk2(re[i][p], r0, r1);
                upk2(im[i][p], u0, u1);
                int m = m0 + 2 * p;
                int riv0 = gldi(ri, (long)(n << 6) + m, rilim);
                int riv1 = gldi(ri, (long)(n << 6) + m + 1, rilim);
                riv0 = riv0 < 0 ? 0 : (riv0 > 224 ? 224 : riv0);
                riv1 = riv1 < 0 ? 0 : (riv1 > 224 ? 224 : riv1);
                float bv0 = gldf(bt, (long)riv0 * 8 + h, btlim);
                float bv1 = gldf(bt, (long)riv1 * 8 + h, btlim);
                sr[n * 66 + m]     = fmaf(r0, scale, bv0);
                sr[n * 66 + m + 1] = fmaf(r1, scale, bv1);
                si[n * 66 + m]     = u0 * scale;
                si[n * 66 + m + 1] = u1 * scale;
            }
        }
    }
    __syncthreads();

    // ---- magnitude softmax + rescale (4 threads/row, 16 cols each) ----
    {
        const int row = t >> 2, c0 = (t & 3) << 4;
        float mags[16], mx = -1e30f;
        #pragma unroll
        for (int c = 0; c < 16; ++c) {
            float arr = sr[row * 66 + c0 + c], aii = si[row * 66 + c0 + c];
            float mg = sqrtf(fmaf(arr, arr, aii * aii));
            mags[c] = mg;
            mx = fmaxf(mx, mg);
        }
        mx = fmaxf(mx, __shfl_xor_sync(0xffffffffu, mx, 1));
        mx = fmaxf(mx, __shfl_xor_sync(0xffffffffu, mx, 2));
        float e[16], ssum = 0.f;
        #pragma unroll
        for (int c = 0; c < 16; ++c) { e[c] = __expf(mags[c] - mx); ssum += e[c]; }
        ssum += __shfl_xor_sync(0xffffffffu, ssum, 1);
        ssum += __shfl_xor_sync(0xffffffffu, ssum, 2);
        float inv = 1.0f / ssum;
        #pragma unroll
        for (int c = 0; c < 16; ++c) {
            float w = (e[c] * inv) / (mags[c] + 1e-8f);
            sr[row * 66 + c0 + c] *= w;
            si[row * 66 + c0 + c] *= w;
        }
    }
    __syncthreads();

    // ---- out = S @ V (FFMA2 over d-pairs); thread = (n, 4 d-pairs) ----
    {
        const int n = t & 63, d0 = (t >> 6) << 3;
        ull o_r[4], o_i[4];
        #pragma unroll
        for (int p = 0; p < 4; ++p) { o_r[p] = 0ull; o_i[p] = 0ull; }
        #pragma unroll 4
        for (int m = 0; m < 64; ++m) {
            float srv = sr[n * 66 + m], siv = si[n * 66 + m];
            ull ps = pk2(srv, srv);
            ull pi = pk2(siv, siv);
            ull ni = pk2(-siv, -siv);
            ulonglong2 vr0 = *(const ulonglong2*)&vrt[m * 36 + d0];
            ulonglong2 vr1 = *(const ulonglong2*)&vrt[m * 36 + d0 + 4];
            ulonglong2 vi0 = *(const ulonglong2*)&vit[m * 36 + d0];
            ulonglong2 vi1 = *(const ulonglong2*)&vit[m * 36 + d0 + 4];
            ull vR[4] = {vr0.x, vr0.y, vr1.x, vr1.y};
            ull vI[4] = {vi0.x, vi0.y, vi1.x, vi1.y};
            #pragma unroll
            for (int p = 0; p < 4; ++p) {
                // or += s_r*v_r - s_i*v_i ; oi += s_r*v_i + s_i*v_r
                o_r[p] = ffma2(ps, vR[p], o_r[p]);
                o_r[p] = ffma2(ni, vI[p], o_r[p]);
                o_i[p] = ffma2(ps, vI[p], o_i[p]);
                o_i[p] = ffma2(pi, vR[p], o_i[p]);
            }
        }
        #pragma unroll
        for (int p = 0; p < 4; ++p) {
            float a0, a1, b0, b1;
            upk2(o_r[p], a0, a1);
            upk2(o_i[p], b0, b1);
            long g0 = (long)(h * 32 + d0 + 2 * p) * 65536 + jb + n;
            g_att_r[g0] = a0;
            g_att_i[g0] = b0;
            g_att_r[g0 + 65536] = a1;
            g_att_i[g0 + 65536] = b1;
        }
    }
}

// ---------------------------------------------------------------------------
// K3: proj GEMM, REAL output only. Tile 64x128, double-buffered.
// Dyn smem: 2 stages x 33792 B = 67584 B. Stage: w_rr[1056] w_ni[1056] | xs.
// ---------------------------------------------------------------------------
#define PROJ_STAGE_ULL 4224

__global__ __launch_bounds__(256, 2) void proj_gemm(
    const float* __restrict__ wr, const float* __restrict__ wi,
    float* __restrict__ out, long wlim, long olim)
{
    extern __shared__ __align__(16) ull smp[];

    const int t = threadIdx.x;
    const long colBase = (long)blockIdx.x * 128;
    const int rowBase = blockIdx.y * 64;

    const int wrow = t >> 2, wk4 = (t & 3) << 2;
    const long wbase = (long)(rowBase + wrow) * 256 + wk4;

    const int k0a = t >> 5;
    const int j0a = (t & 31) << 2;
    const long ja = colBase + j0a;

    const int tx8 = (t & 15) << 3, ty4 = (t >> 4) << 2;

    ull c_re[4][4];
    #pragma unroll
    for (int i = 0; i < 4; ++i)
        #pragma unroll
        for (int j = 0; j < 4; ++j) c_re[i][j] = 0ull;

    float4 wa, wb, xa0, xb0, xa1, xb1;

    wa  = guarded_ld4(wr, wbase, wlim);
    wb  = guarded_ld4(wi, wbase, wlim);
    xa0 = *(const float4*)&g_att_r[(long)k0a * 65536 + ja];
    xb0 = *(const float4*)&g_att_i[(long)k0a * 65536 + ja];
    xa1 = *(const float4*)&g_att_r[(long)(k0a + 8) * 65536 + ja];
    xb1 = *(const float4*)&g_att_i[(long)(k0a + 8) * 65536 + ja];
    {
        ull* bw = smp;
        float* xsr = (float*)(bw + 2112);
        float* xsi = xsr + 2112;
        float wva[4] = {wa.x, wa.y, wa.z, wa.w};
        float wvb[4] = {wb.x, wb.y, wb.z, wb.w};
        #pragma unroll
        for (int q = 0; q < 4; ++q) {
            bw[(wk4 + q) * 66 + wrow]        = pk2(wva[q], wva[q]);
            bw[1056 + (wk4 + q) * 66 + wrow] = pk2(-wvb[q], -wvb[q]);
        }
        *(float4*)&xsr[k0a * 132 + j0a] = xa0;
        *(float4*)&xsi[k0a * 132 + j0a] = xb0;
        *(float4*)&xsr[(k0a + 8) * 132 + j0a] = xa1;
        *(float4*)&xsi[(k0a + 8) * 132 + j0a] = xb1;
    }
    __syncthreads();

    for (int s = 0; s < 16; ++s) {
        if (s < 15) {
            long k0n = (long)(s + 1) * 16;
            wa  = guarded_ld4(wr, wbase + k0n, wlim);
            wb  = guarded_ld4(wi, wbase + k0n, wlim);
            xa0 = *(const float4*)&g_att_r[(k0n + k0a) * 65536 + ja];
            xb0 = *(const float4*)&g_att_i[(k0n + k0a) * 65536 + ja];
            xa1 = *(const float4*)&g_att_r[(k0n + k0a + 8) * 65536 + ja];
            xb1 = *(const float4*)&g_att_i[(k0n + k0a + 8) * 65536 + ja];
        }
        {
            ull* bw = smp + (s & 1) * PROJ_STAGE_ULL;
            const ull* w_rr = bw;
            const ull* w_ni = bw + 1056;
            const float* xsr = (const float*)(bw + 2112);
            const float* xsi = xsr + 2112;
            #pragma unroll
            for (int kk = 0; kk < 16; ++kk) {
                ulonglong2 arr0 = *(const ulonglong2*)&w_rr[kk * 66 + ty4];
                ulonglong2 arr1 = *(const ulonglong2*)&w_rr[kk * 66 + ty4 + 2];
                ulonglong2 ani0 = *(const ulonglong2*)&w_ni[kk * 66 + ty4];
                ulonglong2 ani1 = *(const ulonglong2*)&w_ni[kk * 66 + ty4 + 2];
                ulonglong2 br0 = *(const ulonglong2*)&xsr[kk * 132 + tx8];
                ulonglong2 br1 = *(const ulonglong2*)&xsr[kk * 132 + tx8 + 4];
                ulonglong2 bi0 = *(const ulonglong2*)&xsi[kk * 132 + tx8];
                ulonglong2 bi1 = *(const ulonglong2*)&xsi[kk * 132 + tx8 + 4];
                ull arr[4] = {arr0.x, arr0.y, arr1.x, arr1.y};
                ull ani[4] = {ani0.x, ani0.y, ani1.x, ani1.y};
                ull bre[4] = {br0.x, br0.y, br1.x, br1.y};
                ull bim[4] = {bi0.x, bi0.y, bi1.x, bi1.y};
                #pragma unroll
                for (int i = 0; i < 4; ++i)
                    #pragma unroll
                    for (int j = 0; j < 4; ++j) {
                        c_re[i][j] = ffma2(arr[i], bre[j], c_re[i][j]);
                        c_re[i][j] = ffma2(ani[i], bim[j], c_re[i][j]);
                    }
            }
        }
        if (s < 15) {
            ull* bw = smp + ((s + 1) & 1) * PROJ_STAGE_ULL;
            float* xsr = (float*)(bw + 2112);
            float* xsi = xsr + 2112;
            float wva[4] = {wa.x, wa.y, wa.z, wa.w};
            float wvb[4] = {wb.x, wb.y, wb.z, wb.w};
            #pragma unroll
            for (int q = 0; q < 4; ++q) {
                bw[(wk4 + q) * 66 + wrow]        = pk2(wva[q], wva[q]);
                bw[1056 + (wk4 + q) * 66 + wrow] = pk2(-wvb[q], -wvb[q]);
            }
            *(float4*)&xsr[k0a * 132 + j0a] = xa0;
            *(float4*)&xsi[k0a * 132 + j0a] = xb0;
            *(float4*)&xsr[(k0a + 8) * 132 + j0a] = xa1;
            *(float4*)&xsi[(k0a + 8) * 132 + j0a] = xb1;
        }
        __syncthreads();
    }

    #pragma unroll
    for (int i = 0; i < 4; ++i) {
        long row = rowBase + ty4 + i;
        #pragma unroll
        for (int j = 0; j < 4; ++j) {
            long col = colBase + tx8 + 2 * j;
            long oaddr = (col >> 6) * 16384 + row * 64 + (col & 63);
            if (oaddr + 1 < olim) *(ull*)&out[oaddr] = c_re[i][j];
        }
    }
}

// ---------------------------------------------------------------------------
extern "C" void kernel_launch(void* const* d_in, const int* in_sizes, int n_in,
                              void* d_out, int out_size)
{
    int ord[16];
    int m = n_in < 16 ? n_in : 16;
    for (int i = 0; i < m; ++i) ord[i] = i;
    for (int i = 1; i < m; ++i) {
        int key = ord[i];
        long ks = in_sizes[key];
        int j = i - 1;
        while (j >= 0 && (long)in_sizes[ord[j]] < ks) { ord[j + 1] = ord[j]; --j; }
        ord[j + 1] = key;
    }

    const float *x_r, *x_i, *wq_r, *wq_i, *wp_r, *wp_i, *bt;
    const int* ri;
    long sx, wqlim, wplim, btlim, rilim;

    if (m >= 8) {
        int a0 = ord[0], a1 = ord[1];
        int b0 = ord[2], b1 = ord[3];
        int c0 = ord[4], c1 = ord[5];
        int r0 = ord[6], s0 = ord[7];
        if (a0 > a1) { int tt = a0; a0 = a1; a1 = tt; }
        if (b0 > b1) { int tt = b0; b0 = b1; b1 = tt; }
        if (c0 > c1) { int tt = c0; c0 = c1; c1 = tt; }
        x_r  = (const float*)d_in[a0]; x_i  = (const float*)d_in[a1];
        wq_r = (const float*)d_in[b0]; wq_i = (const float*)d_in[b1];
        wp_r = (const float*)d_in[c0]; wp_i = (const float*)d_in[c1];
        ri   = (const int*)d_in[r0];   bt   = (const float*)d_in[s0];
        sx    = in_sizes[a0];
        wqlim = in_sizes[b0] < 196608 ? in_sizes[b0] : 196608;
        wplim = in_sizes[c0] < 65536  ? in_sizes[c0] : 65536;
        rilim = in_sizes[r0] < 4096   ? in_sizes[r0] : 4096;
        btlim = in_sizes[s0] < 1800   ? in_sizes[s0] : 1800;
    } else {
        x_r  = (const float*)d_in[0]; x_i  = (const float*)d_in[1];
        wq_r = (const float*)d_in[2]; wq_i = (const float*)d_in[3];
        wp_r = (const float*)d_in[4]; wp_i = (const float*)d_in[5];
        bt   = (const float*)d_in[6]; ri   = (const int*)d_in[7];
        sx = 16777216; wqlim = 196608; wplim = 65536; rilim = 4096; btlim = 1800;
    }
    float* out = (float*)d_out;

    long B = sx / 16384;
    if (B < 1) B = 1;
    if (B > 1024) B = 1024;
    long xlim = B * 16384;
    if (xlim > sx) xlim = sx;
    long Jtot = B * 64;
    unsigned gx = (unsigned)((Jtot + 127) / 128);

    long olim = (long)out_size;
    long need = B * 16384;
    if (olim > need) olim = need;
    if (olim < 0) olim = 0;

    const int qkv_smem  = 84480;
    const int attn_smem = 84992;
    const int proj_smem = 67584;
    cudaFuncSetAttribute(qkv_gemm,
                         cudaFuncAttributeMaxDynamicSharedMemorySize, qkv_smem);
    cudaFuncSetAttribute(attn_kernel,
                         cudaFuncAttributeMaxDynamicSharedMemorySize, attn_smem);
    cudaFuncSetAttribute(proj_gemm,
                         cudaFuncAttributeMaxDynamicSharedMemorySize, proj_smem);

    qkv_gemm<<<dim3(gx, 12), 256, qkv_smem>>>(wq_r, wq_i, x_r, x_i, wqlim, xlim);
    attn_kernel<<<dim3((unsigned)B, 8), 256, attn_smem>>>(bt, ri, btlim, rilim);
    proj_gemm<<<dim3(gx, 4), 256, proj_smem>>>(wp_r, wp_i, out, wplim, olim);
}